// round 7
// baseline (speedup 1.0000x reference)
#include <cuda_runtime.h>
#include <cuda_fp16.h>
#include <stdint.h>

#define NUM_USERS 100000
#define N_NODES   150000
#define D         64
#define D4        16          // float4 per fp32 row
#define DH2       16          // uint2 (=4 halfs) per fp16 row
#define E_EDGES   1200000

// ---------------- device scratch (allocation-free) ----------------
__device__ uint2 g_eh[N_NODES * DH2];      // emb converted to fp16
__device__ uint2 g_h0[N_NODES * DH2];      // x1 (fp16)
__device__ uint2 g_h1[N_NODES * DH2];      // x2 (fp16)
__device__ int   g_degi[2 * N_NODES];      // [0,N): deg_row  [N,2N): deg_col
__device__ float g_inv [2 * N_NODES];      // rsqrt(deg) or 0
__device__ int   g_offs[N_NODES];          // CSR start per dst node (disjoint ranges)
__device__ int   g_cursor[N_NODES];        // fill cursors
__device__ int2  g_csr[E_EDGES];           // packed {src_row, inv_row_bits}
__device__ int   g_total;                  // range allocator

// ---------------- setup kernels ----------------

__global__ void k_deg(const int* __restrict__ row, const int* __restrict__ col) {
    int e = blockIdx.x * blockDim.x + threadIdx.x;
    if (e == 0) g_total = 0;                 // reset allocator each replay
    if (e < E_EDGES) {
        atomicAdd(&g_degi[row[e]], 1);
        atomicAdd(&g_degi[N_NODES + col[e]], 1);
    }
}

// Fused: inv-sqrt transform + disjoint CSR range allocation
// (warp scan + block aggregation -> 1 atomic/block).
__global__ void k_alloc() {
    __shared__ int s_wtot[8];
    __shared__ int s_base;
    int n    = blockIdx.x * 256 + threadIdx.x;
    int lane = threadIdx.x & 31;
    int wid  = threadIdx.x >> 5;

    int dc = 0;
    if (n < N_NODES) {
        int dr = g_degi[n];
        dc     = g_degi[N_NODES + n];
        g_inv[n]           = (dr > 0) ? rsqrtf((float)dr) : 0.0f;
        g_inv[N_NODES + n] = (dc > 0) ? rsqrtf((float)dc) : 0.0f;
    }

    int x = dc;                               // warp inclusive scan
    #pragma unroll
    for (int o = 1; o < 32; o <<= 1) {
        int y = __shfl_up_sync(0xffffffffu, x, o);
        if (lane >= o) x += y;
    }
    if (lane == 31) s_wtot[wid] = x;
    __syncthreads();
    if (wid == 0) {
        int v = (lane < 8) ? s_wtot[lane] : 0;
        #pragma unroll
        for (int o = 1; o < 8; o <<= 1) {
            int y = __shfl_up_sync(0xffffffffu, v, o);
            if (lane >= o) v += y;
        }
        if (lane < 8) s_wtot[lane] = v;
        if (lane == 7) s_base = atomicAdd(&g_total, v);
    }
    __syncthreads();
    int base = s_base + (wid > 0 ? s_wtot[wid - 1] : 0);
    if (n < N_NODES) {
        int excl = base + x - dc;
        g_offs[n]   = excl;
        g_cursor[n] = excl;
    }
}

// CSR fill: weight carries ONLY inv_row[r]; inv_col is hoisted in the layer.
__global__ void k_fill(const int* __restrict__ row, const int* __restrict__ col) {
    int e = blockIdx.x * blockDim.x + threadIdx.x;
    if (e < E_EDGES) {
        int r = row[e], c = col[e];
        int slot = atomicAdd(&g_cursor[c], 1);
        g_csr[slot] = make_int2(r, __float_as_int(__ldg(&g_inv[r])));
    }
}

// emb fp32 -> fp16 copy
__global__ void k_cvt(const float4* __restrict__ src, uint2* __restrict__ dst) {
    int i = blockIdx.x * blockDim.x + threadIdx.x;
    if (i < N_NODES * D4) {
        float4 v = __ldg(&src[i]);
        __half2 h0 = __float22half2_rn(make_float2(v.x, v.y));
        __half2 h1 = __float22half2_rn(make_float2(v.z, v.w));
        uint2 o;
        o.x = *reinterpret_cast<unsigned*>(&h0);
        o.y = *reinterpret_cast<unsigned*>(&h1);
        dst[i] = o;
    }
}

// ---------------- propagation layer: 16-lane-per-node pull, fp16 ----------
// Lane q owns halfs [4q,4q+4) (uint2, 8B); the 16-lane gather hits one 128B line.
// 2-wide software pipeline: two independent gathers in flight per thread.
// acc scaled by inv_col[n] once at the end.
// FINAL=0: dst[n] = half(inv_c * acc)
// FINAL=1: out[n] = (emb[n] + x1h[n] + x2h[n] + inv_c*acc) * 0.25
template<int FINAL>
__global__ void k_layerh(const uint2* __restrict__ src,
                         uint2* __restrict__ dst,
                         const float4* __restrict__ emb,
                         const uint2* __restrict__ xa,
                         float4* __restrict__ out) {
    int t = blockIdx.x * blockDim.x + threadIdx.x;
    int n = t >> 4;
    int q = t & 15;
    if (n >= N_NODES) return;

    int   beg   = __ldg(&g_offs[n]);
    int   d     = __ldg(&g_degi[N_NODES + n]);
    float inv_c = __ldg(&g_inv[N_NODES + n]);

    float2 a0 = make_float2(0.f, 0.f);
    float2 a1 = make_float2(0.f, 0.f);

    int2 e0, e1;
    if (d > 0) e0 = __ldg(&g_csr[beg]);
    if (d > 1) e1 = __ldg(&g_csr[beg + 1]);

    int j = 0;
    for (; j + 2 <= d; j += 2) {
        uint2 v0 = __ldg(&src[e0.x * DH2 + q]);
        uint2 v1 = __ldg(&src[e1.x * DH2 + q]);
        float w0 = __int_as_float(e0.y);
        float w1 = __int_as_float(e1.y);
        if (j + 2 < d) e0 = __ldg(&g_csr[beg + j + 2]);
        if (j + 3 < d) e1 = __ldg(&g_csr[beg + j + 3]);
        float2 f;
        f = __half22float2(*reinterpret_cast<__half2*>(&v0.x));
        a0.x = fmaf(w0, f.x, a0.x);  a0.y = fmaf(w0, f.y, a0.y);
        f = __half22float2(*reinterpret_cast<__half2*>(&v0.y));
        a1.x = fmaf(w0, f.x, a1.x);  a1.y = fmaf(w0, f.y, a1.y);
        f = __half22float2(*reinterpret_cast<__half2*>(&v1.x));
        a0.x = fmaf(w1, f.x, a0.x);  a0.y = fmaf(w1, f.y, a0.y);
        f = __half22float2(*reinterpret_cast<__half2*>(&v1.y));
        a1.x = fmaf(w1, f.x, a1.x);  a1.y = fmaf(w1, f.y, a1.y);
    }
    if (j < d) {                      // odd tail: record sits in e0
        uint2 v0 = __ldg(&src[e0.x * DH2 + q]);
        float w0 = __int_as_float(e0.y);
        float2 f;
        f = __half22float2(*reinterpret_cast<__half2*>(&v0.x));
        a0.x = fmaf(w0, f.x, a0.x);  a0.y = fmaf(w0, f.y, a0.y);
        f = __half22float2(*reinterpret_cast<__half2*>(&v0.y));
        a1.x = fmaf(w0, f.x, a1.x);  a1.y = fmaf(w0, f.y, a1.y);
    }

    a0.x *= inv_c; a0.y *= inv_c; a1.x *= inv_c; a1.y *= inv_c;

    int oi = n * DH2 + q;
    if (FINAL == 0) {
        __half2 h0 = __float22half2_rn(a0);
        __half2 h1 = __float22half2_rn(a1);
        uint2 o;
        o.x = *reinterpret_cast<unsigned*>(&h0);
        o.y = *reinterpret_cast<unsigned*>(&h1);
        dst[oi] = o;
    } else {
        float4 em = __ldg(&emb[oi]);
        uint2 va = __ldg(&xa[oi]);    // x1h
        uint2 vb = __ldg(&src[oi]);   // x2h
        float2 fa0 = __half22float2(*reinterpret_cast<__half2*>(&va.x));
        float2 fa1 = __half22float2(*reinterpret_cast<__half2*>(&va.y));
        float2 fb0 = __half22float2(*reinterpret_cast<__half2*>(&vb.x));
        float2 fb1 = __half22float2(*reinterpret_cast<__half2*>(&vb.y));
        const float s = 0.25f;
        out[oi] = make_float4((em.x + fa0.x + fb0.x + a0.x) * s,
                              (em.y + fa0.y + fb0.y + a0.y) * s,
                              (em.z + fa1.x + fb1.x + a1.x) * s,
                              (em.w + fa1.y + fb1.y + a1.y) * s);
    }
}

// ---------------- launch ----------------

extern "C" void kernel_launch(void* const* d_in, const int* in_sizes, int n_in,
                              void* d_out, int out_size) {
    const int*   edge = (const int*)d_in[0];   // [2, E]
    const float* emb  = (const float*)d_in[1]; // [N, 64]
    float*       out  = (float*)d_out;

    const int* row = edge;
    const int* col = edge + E_EDGES;

    uint2* ehp; cudaGetSymbolAddress((void**)&ehp, g_eh);
    uint2* h0p; cudaGetSymbolAddress((void**)&h0p, g_h0);
    uint2* h1p; cudaGetSymbolAddress((void**)&h1p, g_h1);
    int*  degp; cudaGetSymbolAddress((void**)&degp, g_degi);

    const int TB = 256;
    const int gE    = (E_EDGES + TB - 1) / TB;
    const int gN    = (N_NODES + TB - 1) / TB;
    const int gCvt  = (N_NODES * D4 + TB - 1) / TB;
    const int gLyr  = (N_NODES * 16 + TB - 1) / TB;

    // CSR build + fp16 conversion of emb
    cudaMemsetAsync(degp, 0, 2 * N_NODES * sizeof(int));
    k_cvt<<<gCvt, TB>>>((const float4*)emb, ehp);
    k_deg<<<gE, TB>>>(row, col);
    k_alloc<<<gN, TB>>>();                 // fused inv + range allocation
    k_fill<<<gE, TB>>>(row, col);

    // 3 propagation layers; out accumulation fused into final epilogue
    k_layerh<0><<<gLyr, TB>>>(ehp, h0p, nullptr, nullptr, nullptr);
    k_layerh<0><<<gLyr, TB>>>(h0p, h1p, nullptr, nullptr, nullptr);
    k_layerh<1><<<gLyr, TB>>>(h1p, nullptr, (const float4*)emb, h0p, (float4*)out);
}

// round 8
// speedup vs baseline: 1.2115x; 1.2115x over previous
#include <cuda_runtime.h>
#include <cuda_fp16.h>
#include <stdint.h>

#define NUM_USERS 100000
#define N_NODES   150000
#define D         64
#define D4        16          // float4 per fp32 row
#define DH2       16          // uint2 (=4 halfs) per fp16 row
#define E_EDGES   1200000

// ---------------- device scratch (allocation-free) ----------------
__device__ uint2 g_eh[N_NODES * DH2];      // emb converted to fp16
__device__ uint2 g_h0[N_NODES * DH2];      // x1 (fp16)
__device__ uint2 g_h1[N_NODES * DH2];      // x2 (fp16)
__device__ int   g_degi[2 * N_NODES];      // [0,N): deg_row  [N,2N): deg_col
__device__ float g_inv [2 * N_NODES];      // rsqrt(deg) or 0
__device__ int   g_offs[N_NODES];          // CSR start per dst node (disjoint ranges)
__device__ int   g_cursor[N_NODES];        // fill cursors
__device__ int2  g_csr[E_EDGES];           // packed {src_row, inv_row_bits}
__device__ int   g_total;                  // range allocator

// ---------------- setup kernels ----------------

// Fused: emb fp32->fp16 convert (2.4M threads) + degree count (first 1.2M)
__global__ void k_setup(const float4* __restrict__ src, uint2* __restrict__ dst,
                        const int* __restrict__ row, const int* __restrict__ col) {
    int i = blockIdx.x * blockDim.x + threadIdx.x;
    if (i == 0) g_total = 0;
    if (i < N_NODES * D4) {
        float4 v = __ldg(&src[i]);
        __half2 h0 = __float22half2_rn(make_float2(v.x, v.y));
        __half2 h1 = __float22half2_rn(make_float2(v.z, v.w));
        uint2 o;
        o.x = *reinterpret_cast<unsigned*>(&h0);
        o.y = *reinterpret_cast<unsigned*>(&h1);
        dst[i] = o;
    }
    if (i < E_EDGES) {
        atomicAdd(&g_degi[row[i]], 1);
        atomicAdd(&g_degi[N_NODES + col[i]], 1);
    }
}

// Fused: inv-sqrt transform + disjoint CSR range allocation
// (warp scan + block aggregation -> 1 atomic/block).
__global__ void k_alloc() {
    __shared__ int s_wtot[8];
    __shared__ int s_base;
    int n    = blockIdx.x * 256 + threadIdx.x;
    int lane = threadIdx.x & 31;
    int wid  = threadIdx.x >> 5;

    int dc = 0;
    if (n < N_NODES) {
        int dr = g_degi[n];
        dc     = g_degi[N_NODES + n];
        g_inv[n]           = (dr > 0) ? rsqrtf((float)dr) : 0.0f;
        g_inv[N_NODES + n] = (dc > 0) ? rsqrtf((float)dc) : 0.0f;
    }

    int x = dc;                               // warp inclusive scan
    #pragma unroll
    for (int o = 1; o < 32; o <<= 1) {
        int y = __shfl_up_sync(0xffffffffu, x, o);
        if (lane >= o) x += y;
    }
    if (lane == 31) s_wtot[wid] = x;
    __syncthreads();
    if (wid == 0) {
        int v = (lane < 8) ? s_wtot[lane] : 0;
        #pragma unroll
        for (int o = 1; o < 8; o <<= 1) {
            int y = __shfl_up_sync(0xffffffffu, v, o);
            if (lane >= o) v += y;
        }
        if (lane < 8) s_wtot[lane] = v;
        if (lane == 7) s_base = atomicAdd(&g_total, v);
    }
    __syncthreads();
    int base = s_base + (wid > 0 ? s_wtot[wid - 1] : 0);
    if (n < N_NODES) {
        int excl = base + x - dc;
        g_offs[n]   = excl;
        g_cursor[n] = excl;
    }
}

// CSR fill: weight carries ONLY inv_row[r]; inv_col is hoisted in the layer.
__global__ void k_fill(const int* __restrict__ row, const int* __restrict__ col) {
    int e = blockIdx.x * blockDim.x + threadIdx.x;
    if (e < E_EDGES) {
        int r = row[e], c = col[e];
        int slot = atomicAdd(&g_cursor[c], 1);
        g_csr[slot] = make_int2(r, __float_as_int(__ldg(&g_inv[r])));
    }
}

// ---------------- propagation layer: 16-lane-per-node pull, fp16 ----------
// Lane q owns halfs [4q,4q+4) (uint2, 8B); the 16-lane gather hits one 128B line.
// R6-proven 1-deep software prefetch: next record overlaps current vector load.
// acc scaled by inv_col[n] once at the end.
// FINAL=0: dst[n] = half(inv_c * acc)
// FINAL=1: out[n] = (emb[n] + x1h[n] + x2h[n] + inv_c*acc) * 0.25
template<int FINAL>
__global__ void k_layerh(const uint2* __restrict__ src,
                         uint2* __restrict__ dst,
                         const float4* __restrict__ emb,
                         const uint2* __restrict__ xa,
                         float4* __restrict__ out) {
    int t = blockIdx.x * blockDim.x + threadIdx.x;
    int n = t >> 4;
    int q = t & 15;
    if (n >= N_NODES) return;

    int   beg   = __ldg(&g_offs[n]);
    int   d     = __ldg(&g_degi[N_NODES + n]);
    float inv_c = __ldg(&g_inv[N_NODES + n]);

    float2 a0 = make_float2(0.f, 0.f);
    float2 a1 = make_float2(0.f, 0.f);

    int2 e;
    if (d > 0) e = __ldg(&g_csr[beg]);            // software prefetch pipeline
    for (int j = 0; j < d; ++j) {
        int   r = e.x;
        float w = __int_as_float(e.y);
        if (j + 1 < d) e = __ldg(&g_csr[beg + j + 1]);
        uint2 v = __ldg(&src[r * DH2 + q]);
        float2 f0 = __half22float2(*reinterpret_cast<__half2*>(&v.x));
        float2 f1 = __half22float2(*reinterpret_cast<__half2*>(&v.y));
        a0.x = fmaf(w, f0.x, a0.x);
        a0.y = fmaf(w, f0.y, a0.y);
        a1.x = fmaf(w, f1.x, a1.x);
        a1.y = fmaf(w, f1.y, a1.y);
    }

    a0.x *= inv_c; a0.y *= inv_c; a1.x *= inv_c; a1.y *= inv_c;

    int oi = n * DH2 + q;
    if (FINAL == 0) {
        __half2 h0 = __float22half2_rn(a0);
        __half2 h1 = __float22half2_rn(a1);
        uint2 o;
        o.x = *reinterpret_cast<unsigned*>(&h0);
        o.y = *reinterpret_cast<unsigned*>(&h1);
        dst[oi] = o;
    } else {
        float4 em = __ldg(&emb[oi]);
        uint2 va = __ldg(&xa[oi]);    // x1h
        uint2 vb = __ldg(&src[oi]);   // x2h
        float2 fa0 = __half22float2(*reinterpret_cast<__half2*>(&va.x));
        float2 fa1 = __half22float2(*reinterpret_cast<__half2*>(&va.y));
        float2 fb0 = __half22float2(*reinterpret_cast<__half2*>(&vb.x));
        float2 fb1 = __half22float2(*reinterpret_cast<__half2*>(&vb.y));
        const float s = 0.25f;
        out[oi] = make_float4((em.x + fa0.x + fb0.x + a0.x) * s,
                              (em.y + fa0.y + fb0.y + a0.y) * s,
                              (em.z + fa1.x + fb1.x + a1.x) * s,
                              (em.w + fa1.y + fb1.y + a1.y) * s);
    }
}

// ---------------- launch ----------------

extern "C" void kernel_launch(void* const* d_in, const int* in_sizes, int n_in,
                              void* d_out, int out_size) {
    const int*   edge = (const int*)d_in[0];   // [2, E]
    const float* emb  = (const float*)d_in[1]; // [N, 64]
    float*       out  = (float*)d_out;

    const int* row = edge;
    const int* col = edge + E_EDGES;

    uint2* ehp; cudaGetSymbolAddress((void**)&ehp, g_eh);
    uint2* h0p; cudaGetSymbolAddress((void**)&h0p, g_h0);
    uint2* h1p; cudaGetSymbolAddress((void**)&h1p, g_h1);
    int*  degp; cudaGetSymbolAddress((void**)&degp, g_degi);

    const int TB = 256;
    const int gE    = (E_EDGES + TB - 1) / TB;
    const int gN    = (N_NODES + TB - 1) / TB;
    const int gBig  = (N_NODES * D4 + TB - 1) / TB;   // 2.4M threads: cvt + deg
    const int gLyr  = (N_NODES * 16 + TB - 1) / TB;

    // CSR build + fp16 conversion (fused)
    cudaMemsetAsync(degp, 0, 2 * N_NODES * sizeof(int));
    k_setup<<<gBig, TB>>>((const float4*)emb, ehp, row, col);
    k_alloc<<<gN, TB>>>();                 // fused inv + range allocation
    k_fill<<<gE, TB>>>(row, col);

    // 3 propagation layers; out accumulation fused into final epilogue
    k_layerh<0><<<gLyr, TB>>>(ehp, h0p, nullptr, nullptr, nullptr);
    k_layerh<0><<<gLyr, TB>>>(h0p, h1p, nullptr, nullptr, nullptr);
    k_layerh<1><<<gLyr, TB>>>(h1p, nullptr, (const float4*)emb, h0p, (float4*)out);
}

// round 9
// speedup vs baseline: 1.2149x; 1.0028x over previous
#include <cuda_runtime.h>
#include <cuda_fp16.h>
#include <stdint.h>

#define NUM_USERS 100000
#define N_NODES   150000
#define D         64
#define D4        16          // float4 per fp32 row
#define DH2       16          // uint2 (=4 halfs) per fp16 row
#define E_EDGES   1200000

// ---------------- device scratch (allocation-free) ----------------
__device__ uint2 g_s0[N_NODES * DH2];      // x~0 = emb * inv_r   (fp16, scaled)
__device__ uint2 g_s1[N_NODES * DH2];      // x~1 = x1 * inv_r
__device__ uint2 g_s2[N_NODES * DH2];      // x~2 = x2 * inv_r
__device__ uint2 g_t1[N_NODES * DH2];      // x1 (true, fp16)
__device__ uint2 g_t2[N_NODES * DH2];      // x2 (true, fp16)
__device__ int   g_degi[2 * N_NODES];      // [0,N): deg_row  [N,2N): deg_col
__device__ float g_inv [2 * N_NODES];      // rsqrt(deg) or 0
__device__ int   g_offs[N_NODES];          // CSR start per dst node (disjoint ranges)
__device__ int   g_cursor[N_NODES];        // fill cursors
__device__ int   g_csr[E_EDGES + 1];       // src row only (+1 pad: unconditional prefetch)
__device__ int   g_total;                  // range allocator

// convert half2 (as u32) to packed f32x2 and accumulate: acc += {lo,hi}
__device__ __forceinline__ void acc_h2(unsigned long long& acc, unsigned h2) {
    asm("{\n\t"
        ".reg .b16 lo, hi;\n\t"
        ".reg .f32 f0, f1;\n\t"
        ".reg .b64 v;\n\t"
        "mov.b32 {lo, hi}, %1;\n\t"
        "cvt.f32.f16 f0, lo;\n\t"
        "cvt.f32.f16 f1, hi;\n\t"
        "mov.b64 v, {f0, f1};\n\t"
        "add.rn.f32x2 %0, %0, v;\n\t"
        "}" : "+l"(acc) : "r"(h2));
}

__device__ __forceinline__ float2 unpack_x2(unsigned long long a) {
    float2 r;
    asm("mov.b64 {%0, %1}, %2;" : "=f"(r.x), "=f"(r.y) : "l"(a));
    return r;
}

__device__ __forceinline__ uint2 pack_h4(float2 a, float2 b) {
    __half2 h0 = __float22half2_rn(a);
    __half2 h1 = __float22half2_rn(b);
    uint2 o;
    o.x = *reinterpret_cast<unsigned*>(&h0);
    o.y = *reinterpret_cast<unsigned*>(&h1);
    return o;
}

__device__ __forceinline__ float2 unpack_h2(unsigned h) {
    return __half22float2(*reinterpret_cast<__half2*>(&h));
}

// ---------------- setup kernels ----------------

__global__ void k_deg(const int* __restrict__ row, const int* __restrict__ col) {
    int e = blockIdx.x * blockDim.x + threadIdx.x;
    if (e == 0) g_total = 0;
    if (e < E_EDGES) {
        atomicAdd(&g_degi[row[e]], 1);
        atomicAdd(&g_degi[N_NODES + col[e]], 1);
    }
}

// Fused: inv-sqrt transform + disjoint CSR range allocation
// (warp scan + block aggregation -> 1 atomic/block).
__global__ void k_alloc() {
    __shared__ int s_wtot[8];
    __shared__ int s_base;
    int n    = blockIdx.x * 256 + threadIdx.x;
    int lane = threadIdx.x & 31;
    int wid  = threadIdx.x >> 5;

    int dc = 0;
    if (n < N_NODES) {
        int dr = g_degi[n];
        dc     = g_degi[N_NODES + n];
        g_inv[n]           = (dr > 0) ? rsqrtf((float)dr) : 0.0f;
        g_inv[N_NODES + n] = (dc > 0) ? rsqrtf((float)dc) : 0.0f;
    }

    int x = dc;                               // warp inclusive scan
    #pragma unroll
    for (int o = 1; o < 32; o <<= 1) {
        int y = __shfl_up_sync(0xffffffffu, x, o);
        if (lane >= o) x += y;
    }
    if (lane == 31) s_wtot[wid] = x;
    __syncthreads();
    if (wid == 0) {
        int v = (lane < 8) ? s_wtot[lane] : 0;
        #pragma unroll
        for (int o = 1; o < 8; o <<= 1) {
            int y = __shfl_up_sync(0xffffffffu, v, o);
            if (lane >= o) v += y;
        }
        if (lane < 8) s_wtot[lane] = v;
        if (lane == 7) s_base = atomicAdd(&g_total, v);
    }
    __syncthreads();
    int base = s_base + (wid > 0 ? s_wtot[wid - 1] : 0);
    if (n < N_NODES) {
        int excl = base + x - dc;
        g_offs[n]   = excl;
        g_cursor[n] = excl;
    }
}

// CSR fill: record is JUST the source row (4 bytes).
__global__ void k_fill(const int* __restrict__ row, const int* __restrict__ col) {
    int e = blockIdx.x * blockDim.x + threadIdx.x;
    if (e < E_EDGES) {
        int slot = atomicAdd(&g_cursor[col[e]], 1);
        g_csr[slot] = row[e];
    }
}

// x~0 = emb * inv_row, fp16
__global__ void k_cvt() {
    extern __shared__ char dummy[];
    // placeholder to keep signature simple
}

__global__ void k_cvt0(const float4* __restrict__ emb) {
    int i = blockIdx.x * blockDim.x + threadIdx.x;
    if (i < N_NODES * D4) {
        int n = i >> 4;
        float w = __ldg(&g_inv[n]);
        float4 v = __ldg(&emb[i]);
        g_s0[i] = pack_h4(make_float2(v.x * w, v.y * w),
                          make_float2(v.z * w, v.w * w));
    }
}

// ---------------- propagation layer: 16-lane-per-node pull, fp16 ----------
// Lane q owns halfs [4q,4q+4) (uint2, 8B). Inner loop is a PURE SUM of
// pre-scaled vectors: 4-byte record, no weight, unconditional 1-deep prefetch
// (csr padded by 1), f32x2 packed adds.
// FINAL=0: x = acc*inv_c;  dstT = half(x);  dstS = half(x*inv_r)
// FINAL=1: out = (emb + t1 + t2 + acc*inv_c) * 0.25
template<int FINAL>
__global__ void k_layerh(const uint2* __restrict__ src,
                         uint2* __restrict__ dstS,
                         uint2* __restrict__ dstT,
                         const float4* __restrict__ emb,
                         const uint2* __restrict__ t1,
                         const uint2* __restrict__ t2,
                         float4* __restrict__ out) {
    int t = blockIdx.x * blockDim.x + threadIdx.x;
    int n = t >> 4;
    int q = t & 15;
    if (n >= N_NODES) return;

    int beg = __ldg(&g_offs[n]);
    int d   = __ldg(&g_degi[N_NODES + n]);

    unsigned long long a0 = 0ull, a1 = 0ull;   // packed f32x2 accumulators

    int r = 0;
    if (d > 0) r = __ldg(&g_csr[beg]);
    for (int j = 0; j < d; ++j) {
        int rn = __ldg(&g_csr[beg + j + 1]);   // pad makes this always safe
        uint2 v = __ldg(&src[r * DH2 + q]);
        acc_h2(a0, v.x);
        acc_h2(a1, v.y);
        r = rn;
    }

    float inv_c = __ldg(&g_inv[N_NODES + n]);
    float2 f0 = unpack_x2(a0);
    float2 f1 = unpack_x2(a1);
    f0.x *= inv_c; f0.y *= inv_c; f1.x *= inv_c; f1.y *= inv_c;   // true x_k

    int oi = n * DH2 + q;
    if (FINAL == 0) {
        float inv_r = __ldg(&g_inv[n]);
        dstT[oi] = pack_h4(f0, f1);
        dstS[oi] = pack_h4(make_float2(f0.x * inv_r, f0.y * inv_r),
                           make_float2(f1.x * inv_r, f1.y * inv_r));
    } else {
        float4 em = __ldg(&emb[oi]);
        uint2 va = __ldg(&t1[oi]);
        uint2 vb = __ldg(&t2[oi]);
        float2 fa0 = unpack_h2(va.x), fa1 = unpack_h2(va.y);
        float2 fb0 = unpack_h2(vb.x), fb1 = unpack_h2(vb.y);
        const float s = 0.25f;
        out[oi] = make_float4((em.x + fa0.x + fb0.x + f0.x) * s,
                              (em.y + fa0.y + fb0.y + f0.y) * s,
                              (em.z + fa1.x + fb1.x + f1.x) * s,
                              (em.w + fa1.y + fb1.y + f1.y) * s);
    }
}

// ---------------- launch ----------------

extern "C" void kernel_launch(void* const* d_in, const int* in_sizes, int n_in,
                              void* d_out, int out_size) {
    const int*   edge = (const int*)d_in[0];   // [2, E]
    const float* emb  = (const float*)d_in[1]; // [N, 64]
    float*       out  = (float*)d_out;

    const int* row = edge;
    const int* col = edge + E_EDGES;

    uint2* s0p; cudaGetSymbolAddress((void**)&s0p, g_s0);
    uint2* s1p; cudaGetSymbolAddress((void**)&s1p, g_s1);
    uint2* s2p; cudaGetSymbolAddress((void**)&s2p, g_s2);
    uint2* t1p; cudaGetSymbolAddress((void**)&t1p, g_t1);
    uint2* t2p; cudaGetSymbolAddress((void**)&t2p, g_t2);
    int*  degp; cudaGetSymbolAddress((void**)&degp, g_degi);

    const int TB = 256;
    const int gE    = (E_EDGES + TB - 1) / TB;
    const int gN    = (N_NODES + TB - 1) / TB;
    const int gCvt  = (N_NODES * D4 + TB - 1) / TB;
    const int gLyr  = (N_NODES * 16 + TB - 1) / TB;

    // CSR build + pre-scaled fp16 conversion of emb
    cudaMemsetAsync(degp, 0, 2 * N_NODES * sizeof(int));
    k_deg<<<gE, TB>>>(row, col);
    k_alloc<<<gN, TB>>>();                 // fused inv + range allocation
    k_fill<<<gE, TB>>>(row, col);
    k_cvt0<<<gCvt, TB>>>((const float4*)emb);

    // 3 propagation layers; out accumulation fused into final epilogue
    k_layerh<0><<<gLyr, TB>>>(s0p, s1p, t1p, nullptr, nullptr, nullptr, nullptr);
    k_layerh<0><<<gLyr, TB>>>(s1p, s2p, t2p, nullptr, nullptr, nullptr, nullptr);
    k_layerh<1><<<gLyr, TB>>>(s2p, nullptr, nullptr,
                              (const float4*)emb, t1p, t2p, (float4*)out);
}

// round 11
// speedup vs baseline: 1.2678x; 1.0435x over previous
#include <cuda_runtime.h>
#include <cuda_fp16.h>
#include <stdint.h>

#define NUM_USERS 100000
#define N_NODES   150000
#define D         64
#define D4        16          // float4 per fp32 row
#define DH2       16          // uint2 (=4 halfs) per fp16 row
#define E_EDGES   1200000
#define NBIN      64

// ---------------- device scratch (allocation-free) ----------------
__device__ uint2 g_s0[N_NODES * DH2];      // x~0 = emb * inv_r   (fp16, scaled)
__device__ uint2 g_s1[N_NODES * DH2];      // x~1 = x1 * inv_r
__device__ uint2 g_s2[N_NODES * DH2];      // x~2 = x2 * inv_r
__device__ uint2 g_t1[N_NODES * DH2];      // x1 (true, fp16)
__device__ uint2 g_t2[N_NODES * DH2];      // x2 (true, fp16)
__device__ int   g_degi[2 * N_NODES];      // [0,N): deg_row  [N,2N): deg_col
__device__ float g_inv [2 * N_NODES];      // rsqrt(deg) or 0
__device__ int   g_offs[N_NODES];          // CSR start per dst node (disjoint ranges)
__device__ int   g_cursor[N_NODES];        // fill cursors
__device__ int   g_csr[E_EDGES + 1];       // src row only (+1 pad)
__device__ int   g_total;                  // range allocator
__device__ int   g_hist[NBIN];             // degree histogram
__device__ int   g_bincur[NBIN];           // bin cursors (set by k_scan)
__device__ int   g_perm[N_NODES];          // degree-sorted node order

// ---------------- helpers ----------------

__device__ __forceinline__ void acc_h2(unsigned long long& acc, unsigned h2) {
    asm("{\n\t"
        ".reg .b16 lo, hi;\n\t"
        ".reg .f32 f0, f1;\n\t"
        ".reg .b64 v;\n\t"
        "mov.b32 {lo, hi}, %1;\n\t"
        "cvt.f32.f16 f0, lo;\n\t"
        "cvt.f32.f16 f1, hi;\n\t"
        "mov.b64 v, {f0, f1};\n\t"
        "add.rn.f32x2 %0, %0, v;\n\t"
        "}" : "+l"(acc) : "r"(h2));
}

__device__ __forceinline__ float2 unpack_x2(unsigned long long a) {
    float2 r;
    asm("mov.b64 {%0, %1}, %2;" : "=f"(r.x), "=f"(r.y) : "l"(a));
    return r;
}

__device__ __forceinline__ uint2 pack_h4(float2 a, float2 b) {
    __half2 h0 = __float22half2_rn(a);
    __half2 h1 = __float22half2_rn(b);
    uint2 o;
    o.x = *reinterpret_cast<unsigned*>(&h0);
    o.y = *reinterpret_cast<unsigned*>(&h1);
    return o;
}

__device__ __forceinline__ float2 unpack_h2(unsigned h) {
    return __half22float2(*reinterpret_cast<__half2*>(&h));
}

// ---------------- setup kernels ----------------

__global__ void k_deg(const int* __restrict__ row, const int* __restrict__ col) {
    int e = blockIdx.x * blockDim.x + threadIdx.x;
    if (e == 0) g_total = 0;
    if (e < NBIN) g_hist[e] = 0;            // zeroed before k_alloc increments
    if (e < E_EDGES) {
        atomicAdd(&g_degi[row[e]], 1);
        atomicAdd(&g_degi[N_NODES + col[e]], 1);
    }
}

// Fused: inv-sqrt + CSR range allocation + degree histogram.
__global__ void k_alloc() {
    __shared__ int s_wtot[8];
    __shared__ int s_base;
    __shared__ int s_hist[NBIN];
    int n    = blockIdx.x * 256 + threadIdx.x;
    int lane = threadIdx.x & 31;
    int wid  = threadIdx.x >> 5;
    if (threadIdx.x < NBIN) s_hist[threadIdx.x] = 0;
    __syncthreads();

    int dc = 0;
    if (n < N_NODES) {
        int dr = g_degi[n];
        dc     = g_degi[N_NODES + n];
        g_inv[n]           = (dr > 0) ? rsqrtf((float)dr) : 0.0f;
        g_inv[N_NODES + n] = (dc > 0) ? rsqrtf((float)dc) : 0.0f;
        atomicAdd(&s_hist[min(dc, NBIN - 1)], 1);
    }

    int x = dc;                               // warp inclusive scan
    #pragma unroll
    for (int o = 1; o < 32; o <<= 1) {
        int y = __shfl_up_sync(0xffffffffu, x, o);
        if (lane >= o) x += y;
    }
    if (lane == 31) s_wtot[wid] = x;
    __syncthreads();
    if (wid == 0) {
        int v = (lane < 8) ? s_wtot[lane] : 0;
        #pragma unroll
        for (int o = 1; o < 8; o <<= 1) {
            int y = __shfl_up_sync(0xffffffffu, v, o);
            if (lane >= o) v += y;
        }
        if (lane < 8) s_wtot[lane] = v;
        if (lane == 7) s_base = atomicAdd(&g_total, v);
    }
    __syncthreads();
    int base = s_base + (wid > 0 ? s_wtot[wid - 1] : 0);
    if (n < N_NODES) {
        int excl = base + x - dc;
        g_offs[n]   = excl;
        g_cursor[n] = excl;
    }
    if (threadIdx.x < NBIN && s_hist[threadIdx.x] > 0)
        atomicAdd(&g_hist[threadIdx.x], s_hist[threadIdx.x]);
}

// 64-bin exclusive scan -> bin cursors. 1 block, 64 threads.
__global__ void k_scan() {
    __shared__ int s[NBIN];
    int i = threadIdx.x;
    int v = g_hist[i];
    s[i] = v;
    __syncthreads();
    for (int o = 1; o < NBIN; o <<= 1) {
        int t = (i >= o) ? s[i - o] : 0;
        __syncthreads();
        s[i] += t;
        __syncthreads();
    }
    g_bincur[i] = s[i] - v;                  // exclusive
}

// Block-aggregated counting-sort scatter: perm = nodes ordered by deg_col.
__global__ void k_perm() {
    __shared__ int s_cnt[NBIN];
    __shared__ int s_base[NBIN];
    int i = blockIdx.x * 256 + threadIdx.x;
    if (threadIdx.x < NBIN) s_cnt[threadIdx.x] = 0;
    __syncthreads();
    int b = 0, lr = 0;
    bool ok = (i < N_NODES);
    if (ok) {
        b  = min(g_degi[N_NODES + i], NBIN - 1);
        lr = atomicAdd(&s_cnt[b], 1);
    }
    __syncthreads();
    if (threadIdx.x < NBIN) {
        int c = s_cnt[threadIdx.x];
        s_base[threadIdx.x] = c ? atomicAdd(&g_bincur[threadIdx.x], c) : 0;
    }
    __syncthreads();
    if (ok) g_perm[s_base[b] + lr] = i;
}

// Fused: CSR fill (first 1.2M threads) + emb*inv_r fp16 convert (all 2.4M).
__global__ void k_fillcvt(const int* __restrict__ row, const int* __restrict__ col,
                          const float4* __restrict__ emb) {
    int i = blockIdx.x * blockDim.x + threadIdx.x;
    if (i < E_EDGES) {
        int slot = atomicAdd(&g_cursor[col[i]], 1);
        g_csr[slot] = row[i];
    }
    if (i < N_NODES * D4) {
        int n = i >> 4;
        float w = __ldg(&g_inv[n]);
        float4 v = __ldg(&emb[i]);
        g_s0[i] = pack_h4(make_float2(v.x * w, v.y * w),
                          make_float2(v.z * w, v.w * w));
    }
}

// ---------------- propagation layer: degree-sorted 16-lane-per-node pull ---
// Nodes processed via g_perm: warp-neighbors share (near-)equal degree, so the
// gather loop retires uniformly across the warp. Inner loop: pure fp16 sum of
// pre-scaled vectors, 4-byte records, unconditional 1-deep prefetch.
// FINAL=0: x = acc*inv_c;  dstT = half(x);  dstS = half(x*inv_r)
// FINAL=1: out = (emb + t1 + t2 + acc*inv_c) * 0.25
template<int FINAL>
__global__ void k_layerh(const uint2* __restrict__ src,
                         uint2* __restrict__ dstS,
                         uint2* __restrict__ dstT,
                         const float4* __restrict__ emb,
                         const uint2* __restrict__ t1,
                         const uint2* __restrict__ t2,
                         float4* __restrict__ out) {
    int t = blockIdx.x * blockDim.x + threadIdx.x;
    int slot = t >> 4;
    int q    = t & 15;
    if (slot >= N_NODES) return;
    int n = __ldg(&g_perm[slot]);

    int beg = __ldg(&g_offs[n]);
    int d   = __ldg(&g_degi[N_NODES + n]);

    unsigned long long a0 = 0ull, a1 = 0ull;   // packed f32x2 accumulators

    int r = 0;
    if (d > 0) r = __ldg(&g_csr[beg]);
    for (int j = 0; j < d; ++j) {
        int rn = __ldg(&g_csr[beg + j + 1]);   // pad makes this always safe
        uint2 v = __ldg(&src[r * DH2 + q]);
        acc_h2(a0, v.x);
        acc_h2(a1, v.y);
        r = rn;
    }

    float inv_c = __ldg(&g_inv[N_NODES + n]);
    float2 f0 = unpack_x2(a0);
    float2 f1 = unpack_x2(a1);
    f0.x *= inv_c; f0.y *= inv_c; f1.x *= inv_c; f1.y *= inv_c;   // true x_k

    int oi = n * DH2 + q;
    if (FINAL == 0) {
        float inv_r = __ldg(&g_inv[n]);
        dstT[oi] = pack_h4(f0, f1);
        dstS[oi] = pack_h4(make_float2(f0.x * inv_r, f0.y * inv_r),
                           make_float2(f1.x * inv_r, f1.y * inv_r));
    } else {
        float4 em = __ldg(&emb[oi]);
        uint2 va = __ldg(&t1[oi]);
        uint2 vb = __ldg(&t2[oi]);
        float2 fa0 = unpack_h2(va.x), fa1 = unpack_h2(va.y);
        float2 fb0 = unpack_h2(vb.x), fb1 = unpack_h2(vb.y);
        const float s = 0.25f;
        out[oi] = make_float4((em.x + fa0.x + fb0.x + f0.x) * s,
                              (em.y + fa0.y + fb0.y + f0.y) * s,
                              (em.z + fa1.x + fb1.x + f1.x) * s,
                              (em.w + fa1.y + fb1.y + f1.y) * s);
    }
}

// ---------------- launch ----------------

extern "C" void kernel_launch(void* const* d_in, const int* in_sizes, int n_in,
                              void* d_out, int out_size) {
    const int*   edge = (const int*)d_in[0];   // [2, E]
    const float* emb  = (const float*)d_in[1]; // [N, 64]
    float*       out  = (float*)d_out;

    const int* row = edge;
    const int* col = edge + E_EDGES;

    uint2* s0p; cudaGetSymbolAddress((void**)&s0p, g_s0);
    uint2* s1p; cudaGetSymbolAddress((void**)&s1p, g_s1);
    uint2* s2p; cudaGetSymbolAddress((void**)&s2p, g_s2);
    uint2* t1p; cudaGetSymbolAddress((void**)&t1p, g_t1);
    uint2* t2p; cudaGetSymbolAddress((void**)&t2p, g_t2);
    int*  degp; cudaGetSymbolAddress((void**)&degp, g_degi);

    const int TB = 256;
    const int gE   = (E_EDGES + TB - 1) / TB;
    const int gN   = (N_NODES + TB - 1) / TB;
    const int gBig = (N_NODES * D4 + TB - 1) / TB;   // 2.4M threads
    const int gLyr = (N_NODES * 16 + TB - 1) / TB;

    // CSR build + degree sort + pre-scaled fp16 conversion
    cudaMemsetAsync(degp, 0, 2 * N_NODES * sizeof(int));
    k_deg<<<gE, TB>>>(row, col);
    k_alloc<<<gN, TB>>>();
    k_scan<<<1, NBIN>>>();
    k_perm<<<gN, TB>>>();
    k_fillcvt<<<gBig, TB>>>(row, col, (const float4*)emb);

    // 3 propagation layers; out accumulation fused into final epilogue
    k_layerh<0><<<gLyr, TB>>>(s0p, s1p, t1p, nullptr, nullptr, nullptr, nullptr);
    k_layerh<0><<<gLyr, TB>>>(s1p, s2p, t2p, nullptr, nullptr, nullptr, nullptr);
    k_layerh<1><<<gLyr, TB>>>(s2p, nullptr, nullptr,
                              (const float4*)emb, t1p, t2p, (float4*)out);
}

// round 13
// speedup vs baseline: 1.3519x; 1.0664x over previous
#include <cuda_runtime.h>
#include <cuda_fp16.h>
#include <stdint.h>

#define NUM_USERS 100000
#define N_NODES   150000
#define D         64
#define D4        16          // float4 per fp32 row
#define DH2       16          // uint2 (=4 halfs) per fp16 row
#define E_EDGES   1200000
#define NBIN      64

// ---------------- device scratch (allocation-free) ----------------
__device__ uint2 g_s0[N_NODES * DH2];      // x~0 = emb * inv_r   (fp16, scaled)
__device__ uint2 g_s1[N_NODES * DH2];      // x~1 = x1 * inv_r
__device__ uint2 g_s2[N_NODES * DH2];      // x~2 = x2 * inv_r
__device__ uint2 g_t1[N_NODES * DH2];      // x1 (true, fp16)
__device__ uint2 g_t2[N_NODES * DH2];      // x2 (true, fp16)
__device__ int   g_degi[2 * N_NODES];      // [0,N): deg_row  [N,2N): deg_col
__device__ float g_inv [2 * N_NODES];      // rsqrt(deg) or 0
__device__ int   g_offs[N_NODES];          // CSR start per dst node
__device__ int   g_cursor[N_NODES];        // fill cursors
__device__ int   g_csr[E_EDGES + 2];       // src row only (+2 pad: unpredicated 2-wide prefetch)
__device__ int   g_total;                  // range allocator
__device__ int   g_hist[NBIN];             // degree histogram
__device__ int   g_bincur[NBIN];           // bin cursors (descending layout)
__device__ int   g_perm[N_NODES];          // nodes ordered by deg_col DESC

// ---------------- helpers ----------------

__device__ __forceinline__ void acc_h2(unsigned long long& acc, unsigned h2) {
    asm("{\n\t"
        ".reg .b16 lo, hi;\n\t"
        ".reg .f32 f0, f1;\n\t"
        ".reg .b64 v;\n\t"
        "mov.b32 {lo, hi}, %1;\n\t"
        "cvt.f32.f16 f0, lo;\n\t"
        "cvt.f32.f16 f1, hi;\n\t"
        "mov.b64 v, {f0, f1};\n\t"
        "add.rn.f32x2 %0, %0, v;\n\t"
        "}" : "+l"(acc) : "r"(h2));
}

__device__ __forceinline__ float2 unpack_x2(unsigned long long a) {
    float2 r;
    asm("mov.b64 {%0, %1}, %2;" : "=f"(r.x), "=f"(r.y) : "l"(a));
    return r;
}

__device__ __forceinline__ uint2 pack_h4(float2 a, float2 b) {
    __half2 h0 = __float22half2_rn(a);
    __half2 h1 = __float22half2_rn(b);
    uint2 o;
    o.x = *reinterpret_cast<unsigned*>(&h0);
    o.y = *reinterpret_cast<unsigned*>(&h1);
    return o;
}

__device__ __forceinline__ float2 unpack_h2(unsigned h) {
    return __half22float2(*reinterpret_cast<__half2*>(&h));
}

// ---------------- setup kernels ----------------

__global__ void k_deg(const int* __restrict__ row, const int* __restrict__ col) {
    int e = blockIdx.x * blockDim.x + threadIdx.x;
    if (e == 0) g_total = 0;
    if (e < NBIN) g_hist[e] = 0;
    if (e < E_EDGES) {
        atomicAdd(&g_degi[row[e]], 1);
        atomicAdd(&g_degi[N_NODES + col[e]], 1);
    }
}

// Fused: inv-sqrt + CSR range allocation + degree histogram.
__global__ void k_alloc() {
    __shared__ int s_wtot[8];
    __shared__ int s_base;
    __shared__ int s_hist[NBIN];
    int n    = blockIdx.x * 256 + threadIdx.x;
    int lane = threadIdx.x & 31;
    int wid  = threadIdx.x >> 5;
    if (threadIdx.x < NBIN) s_hist[threadIdx.x] = 0;
    __syncthreads();

    int dc = 0;
    if (n < N_NODES) {
        int dr = g_degi[n];
        dc     = g_degi[N_NODES + n];
        g_inv[n]           = (dr > 0) ? rsqrtf((float)dr) : 0.0f;
        g_inv[N_NODES + n] = (dc > 0) ? rsqrtf((float)dc) : 0.0f;
        atomicAdd(&s_hist[min(dc, NBIN - 1)], 1);
    }

    int x = dc;                               // warp inclusive scan
    #pragma unroll
    for (int o = 1; o < 32; o <<= 1) {
        int y = __shfl_up_sync(0xffffffffu, x, o);
        if (lane >= o) x += y;
    }
    if (lane == 31) s_wtot[wid] = x;
    __syncthreads();
    if (wid == 0) {
        int v = (lane < 8) ? s_wtot[lane] : 0;
        #pragma unroll
        for (int o = 1; o < 8; o <<= 1) {
            int y = __shfl_up_sync(0xffffffffu, v, o);
            if (lane >= o) v += y;
        }
        if (lane < 8) s_wtot[lane] = v;
        if (lane == 7) s_base = atomicAdd(&g_total, v);
    }
    __syncthreads();
    int base = s_base + (wid > 0 ? s_wtot[wid - 1] : 0);
    if (n < N_NODES) {
        int excl = base + x - dc;
        g_offs[n]   = excl;
        g_cursor[n] = excl;
    }
    if (threadIdx.x < NBIN && s_hist[threadIdx.x] > 0)
        atomicAdd(&g_hist[threadIdx.x], s_hist[threadIdx.x]);
}

// 64-bin scan -> DESCENDING bin bases: heavy-degree bins get the lowest slots,
// so heavy warps launch first and don't define the kernel tail.
__global__ void k_scan() {
    __shared__ int s[NBIN];
    int i = threadIdx.x;
    int v = g_hist[i];
    s[i] = v;
    __syncthreads();
    for (int o = 1; o < NBIN; o <<= 1) {
        int t = (i >= o) ? s[i - o] : 0;
        __syncthreads();
        s[i] += t;
        __syncthreads();
    }
    g_bincur[i] = N_NODES - s[i];            // start of bin i, descending layout
}

// Block-aggregated counting-sort scatter.
__global__ void k_perm() {
    __shared__ int s_cnt[NBIN];
    __shared__ int s_base[NBIN];
    int i = blockIdx.x * 256 + threadIdx.x;
    if (threadIdx.x < NBIN) s_cnt[threadIdx.x] = 0;
    __syncthreads();
    int b = 0, lr = 0;
    bool ok = (i < N_NODES);
    if (ok) {
        b  = min(g_degi[N_NODES + i], NBIN - 1);
        lr = atomicAdd(&s_cnt[b], 1);
    }
    __syncthreads();
    if (threadIdx.x < NBIN) {
        int c = s_cnt[threadIdx.x];
        s_base[threadIdx.x] = c ? atomicAdd(&g_bincur[threadIdx.x], c) : 0;
    }
    __syncthreads();
    if (ok) g_perm[s_base[b] + lr] = i;
}

// Fused: CSR fill (first 1.2M threads) + emb*inv_r fp16 convert (all 2.4M).
__global__ void k_fillcvt(const int* __restrict__ row, const int* __restrict__ col,
                          const float4* __restrict__ emb) {
    int i = blockIdx.x * blockDim.x + threadIdx.x;
    if (i < E_EDGES) {
        int slot = atomicAdd(&g_cursor[col[i]], 1);
        g_csr[slot] = row[i];
    }
    if (i < N_NODES * D4) {
        int n = i >> 4;
        float w = __ldg(&g_inv[n]);
        float4 v = __ldg(&emb[i]);
        g_s0[i] = pack_h4(make_float2(v.x * w, v.y * w),
                          make_float2(v.z * w, v.w * w));
    }
}

// ---------------- propagation layer ----------------
// Degree-sorted (desc) 16-lane-per-node pull. 2-wide unpredicated pipeline:
// two vector gathers + two record prefetches in flight every iteration
// (csr padded by 2 so the prefetches never need bounds checks).
// FINAL=0: x = acc*inv_c;  dstT = half(x);  dstS = half(x*inv_r)
// FINAL=1: out = (emb + t1 + t2 + acc*inv_c) * 0.25
template<int FINAL>
__global__ void k_layerh(const uint2* __restrict__ src,
                         uint2* __restrict__ dstS,
                         uint2* __restrict__ dstT,
                         const float4* __restrict__ emb,
                         const uint2* __restrict__ t1,
                         const uint2* __restrict__ t2,
                         float4* __restrict__ out) {
    int t = blockIdx.x * blockDim.x + threadIdx.x;
    int slot = t >> 4;
    int q    = t & 15;
    if (slot >= N_NODES) return;
    int n = __ldg(&g_perm[slot]);

    int beg = __ldg(&g_offs[n]);
    int d   = __ldg(&g_degi[N_NODES + n]);

    unsigned long long a0 = 0ull, a1 = 0ull;   // packed f32x2 accumulators

    int r0 = 0, r1 = 0;
    if (d > 0) {                               // beg+1 safe: csr has +2 pad
        r0 = __ldg(&g_csr[beg]);
        r1 = __ldg(&g_csr[beg + 1]);
    }
    int j = 0;
    for (; j + 1 < d; j += 2) {
        uint2 v0 = __ldg(&src[r0 * DH2 + q]);
        uint2 v1 = __ldg(&src[r1 * DH2 + q]);
        r0 = __ldg(&g_csr[beg + j + 2]);       // unconditional: pad covers it
        r1 = __ldg(&g_csr[beg + j + 3]);
        acc_h2(a0, v0.x);
        acc_h2(a1, v0.y);
        acc_h2(a0, v1.x);
        acc_h2(a1, v1.y);
    }
    if (j < d) {                               // odd tail: record sits in r0
        uint2 v0 = __ldg(&src[r0 * DH2 + q]);
        acc_h2(a0, v0.x);
        acc_h2(a1, v0.y);
    }

    float inv_c = __ldg(&g_inv[N_NODES + n]);
    float2 f0 = unpack_x2(a0);
    float2 f1 = unpack_x2(a1);
    f0.x *= inv_c; f0.y *= inv_c; f1.x *= inv_c; f1.y *= inv_c;   // true x_k

    int oi = n * DH2 + q;
    if (FINAL == 0) {
        float inv_r = __ldg(&g_inv[n]);
        dstT[oi] = pack_h4(f0, f1);
        dstS[oi] = pack_h4(make_float2(f0.x * inv_r, f0.y * inv_r),
                           make_float2(f1.x * inv_r, f1.y * inv_r));
    } else {
        float4 em = __ldg(&emb[oi]);
        uint2 va = __ldg(&t1[oi]);
        uint2 vb = __ldg(&t2[oi]);
        float2 fa0 = unpack_h2(va.x), fa1 = unpack_h2(va.y);
        float2 fb0 = unpack_h2(vb.x), fb1 = unpack_h2(vb.y);
        const float s = 0.25f;
        out[oi] = make_float4((em.x + fa0.x + fb0.x + f0.x) * s,
                              (em.y + fa0.y + fb0.y + f0.y) * s,
                              (em.z + fa1.x + fb1.x + f1.x) * s,
                              (em.w + fa1.y + fb1.y + f1.y) * s);
    }
}

// ---------------- launch ----------------

extern "C" void kernel_launch(void* const* d_in, const int* in_sizes, int n_in,
                              void* d_out, int out_size) {
    const int*   edge = (const int*)d_in[0];   // [2, E]
    const float* emb  = (const float*)d_in[1]; // [N, 64]
    float*       out  = (float*)d_out;

    const int* row = edge;
    const int* col = edge + E_EDGES;

    uint2* s0p; cudaGetSymbolAddress((void**)&s0p, g_s0);
    uint2* s1p; cudaGetSymbolAddress((void**)&s1p, g_s1);
    uint2* s2p; cudaGetSymbolAddress((void**)&s2p, g_s2);
    uint2* t1p; cudaGetSymbolAddress((void**)&t1p, g_t1);
    uint2* t2p; cudaGetSymbolAddress((void**)&t2p, g_t2);
    int*  degp; cudaGetSymbolAddress((void**)&degp, g_degi);

    const int TB = 256;
    const int gE   = (E_EDGES + TB - 1) / TB;
    const int gN   = (N_NODES + TB - 1) / TB;
    const int gBig = (N_NODES * D4 + TB - 1) / TB;   // 2.4M threads
    const int gLyr = (N_NODES * 16 + TB - 1) / TB;

    // CSR build + degree sort (descending) + pre-scaled fp16 conversion
    cudaMemsetAsync(degp, 0, 2 * N_NODES * sizeof(int));
    k_deg<<<gE, TB>>>(row, col);
    k_alloc<<<gN, TB>>>();
    k_scan<<<1, NBIN>>>();
    k_perm<<<gN, TB>>>();
    k_fillcvt<<<gBig, TB>>>(row, col, (const float4*)emb);

    // 3 propagation layers; out accumulation fused into final epilogue
    k_layerh<0><<<gLyr, TB>>>(s0p, s1p, t1p, nullptr, nullptr, nullptr, nullptr);
    k_layerh<0><<<gLyr, TB>>>(s1p, s2p, t2p, nullptr, nullptr, nullptr, nullptr);
    k_layerh<1><<<gLyr, TB>>>(s2p, nullptr, nullptr,
                              (const float4*)emb, t1p, t2p, (float4*)out);
}